// round 3
// baseline (speedup 1.0000x reference)
#include <cuda_runtime.h>
#include <cuda_bf16.h>
#include <math.h>

// Model: BRITS-style recurrent imputation. B=256, T=512, F=64, H=128, gates=512.
// Inputs (metadata order):
//  0 values[B,T,F] 1 masks 2 deltas 3 labels[B,1] 4 is_train[B,1]
//  5 W_dh[H,F] 6 b_dh[H] 7 W_dx[F,F] 8 b_dx[F] 9 W_hr[F,H] 10 b_hr[F]
// 11 W_fr[F,F] 12 b_fr[F] 13 W_wc[F,2F] 14 b_wc[F]
// 15 W_ih[4H,2F] 16 b_ih[4H] 17 W_hh[4H,H] 18 b_hh[4H] 19 W_out[1,H] 20 b_out[1]
// Output: [loss(1), predictions(256), imputations(256*512*64)] = 8388865 floats.

#define Bsz 256
#define Tt  512
#define Ff  64
#define Hh  128
#define Gg  512
#define ROWS 4
#define NCTA (Bsz / ROWS)   // 64

// ---------------- device-global scratch (static, allocation-free) ----------
__device__ __align__(16) float g_W[256 * Gg];   // gates weights k-major [k][out]
__device__ float g_bg[Gg];                      // b_ih + b_hh
__device__ float g_WdhT[Ff * Hh];               // [k][out]
__device__ float g_WhrT[Hh * Ff];
__device__ float g_WfrT[Ff * Ff];               // diag zeroed
__device__ float g_WwcT[2 * Ff * Ff];
__device__ float g_wdx[Ff];                     // diag(W_dx)
__device__ float g_inv_msum[Tt];
__device__ float g_istrain;
__device__ float g_xloss;
__device__ float g_yloss;

// ---------------- f32x2 helpers (Blackwell packed FFMA2) -------------------
__device__ __forceinline__ unsigned long long splat2(float w) {
    unsigned long long r; unsigned int wi = __float_as_uint(w);
    asm("mov.b64 %0, {%1, %2};" : "=l"(r) : "r"(wi), "r"(wi));
    return r;
}
__device__ __forceinline__ unsigned long long fma2(unsigned long long a,
                                                   unsigned long long b,
                                                   unsigned long long c) {
    unsigned long long d;
    asm("fma.rn.f32x2 %0, %1, %2, %3;" : "=l"(d) : "l"(a), "l"(b), "l"(c));
    return d;
}
union F2U { unsigned long long u; float2 f; };

__device__ __forceinline__ float sigm(float x) { return 1.f / (1.f + __expf(-x)); }
__device__ __forceinline__ float tanh_e(float x) { return 1.f - 2.f / (__expf(2.f * x) + 1.f); }

// ---------------- prep: weight transposes ---------------------------------
__global__ void prep_weights(const float* __restrict__ W_dh, const float* __restrict__ W_dx,
                             const float* __restrict__ W_hr, const float* __restrict__ W_fr,
                             const float* __restrict__ W_wc,
                             const float* __restrict__ W_ih, const float* __restrict__ b_ih,
                             const float* __restrict__ W_hh, const float* __restrict__ b_hh) {
    const int idx = blockIdx.x * blockDim.x + threadIdx.x;
    const int stride = gridDim.x * blockDim.x;
    for (int i = idx; i < 256 * Gg; i += stride) {
        int k = i / Gg, o = i % Gg;
        g_W[i] = (k < 128) ? W_ih[o * 128 + k] : W_hh[o * Hh + (k - 128)];
    }
    for (int i = idx; i < Gg; i += stride) g_bg[i] = b_ih[i] + b_hh[i];
    for (int i = idx; i < Ff * Hh; i += stride) { int k = i / Hh, o = i % Hh; g_WdhT[i] = W_dh[o * Ff + k]; }
    for (int i = idx; i < Hh * Ff; i += stride) { int k = i / Ff, o = i % Ff; g_WhrT[i] = W_hr[o * Hh + k]; }
    for (int i = idx; i < Ff * Ff; i += stride) { int k = i / Ff, o = i % Ff; g_WfrT[i] = (o == k) ? 0.f : W_fr[o * Ff + k]; }
    for (int i = idx; i < 2 * Ff * Ff; i += stride) { int k = i / Ff, o = i % Ff; g_WwcT[i] = W_wc[o * (2 * Ff) + k]; }
    for (int i = idx; i < Ff; i += stride) g_wdx[i] = W_dx[i * Ff + i];
}

// ---------------- prep: msum(t), is_train sum, zero accumulators ----------
__global__ void prep_msum(const float* __restrict__ masks, const float* __restrict__ is_train) {
    __shared__ float red[256];
    const int t = blockIdx.x;
    float s = 0.f;
    if (t < Tt) {
        for (int i = threadIdx.x; i < Bsz * Ff; i += 256) {
            int b = i / Ff, f = i % Ff;
            s += masks[(b * Tt + t) * Ff + f];
        }
    } else {
        s = is_train[threadIdx.x];   // blockDim 256 == Bsz
    }
    red[threadIdx.x] = s; __syncthreads();
    for (int off = 128; off > 0; off >>= 1) {
        if (threadIdx.x < off) red[threadIdx.x] += red[threadIdx.x + off];
        __syncthreads();
    }
    if (threadIdx.x == 0) {
        if (t < Tt) g_inv_msum[t] = 1.f / (red[0] + 1e-5f);
        else { g_istrain = red[0]; g_xloss = 0.f; g_yloss = 0.f; }
    }
}

// ---------------- main persistent scan kernel -----------------------------
__global__ __launch_bounds__(256, 1)
void brits_main(const float* __restrict__ values, const float* __restrict__ masks,
                const float* __restrict__ deltas, const float* __restrict__ labels,
                const float* __restrict__ is_train,
                const float* __restrict__ b_dh, const float* __restrict__ b_dx,
                const float* __restrict__ b_hr, const float* __restrict__ b_fr,
                const float* __restrict__ b_wc,
                const float* __restrict__ W_out, const float* __restrict__ b_out,
                float* __restrict__ out) {
    // actT layout [k][r]: k 0..63 = c_c, 64..127 = m, 128..255 = h (persistent)
    __shared__ __align__(16) float actT[256 * 4];
    __shared__ __align__(16) float cT[128 * 4];
    __shared__ __align__(16) float dT[64 * 4];
    __shared__ __align__(16) float xT[64 * 4];
    __shared__ __align__(16) float mT[64 * 4];
    __shared__ __align__(16) float gxT[64 * 4];
    __shared__ __align__(16) float xcT[64 * 4];
    __shared__ __align__(16) float gT[512 * 4];   // gates pre-activation [out][r]
    __shared__ float red[256];

    const int tid = threadIdx.x;
    const int b0 = blockIdx.x * ROWS;
    const int fr_f = tid & 63;    // F-elementwise mapping
    const int fr_r = tid >> 6;
    const int hu = tid & 127;     // H-output mapping
    const int hrp = tid >> 7;     // row pair 0/1

    // init h = c = 0 (each thread inits 2 h and 2 c entries)
    actT[(128 + hu) * 4 + 2 * hrp]     = 0.f;
    actT[(128 + hu) * 4 + 2 * hrp + 1] = 0.f;
    cT[hu * 4 + 2 * hrp]     = 0.f;
    cT[hu * 4 + 2 * hrp + 1] = 0.f;
    float lacc = 0.f;
    __syncthreads();

    int gidx = ((b0 + fr_r) * Tt) * Ff + fr_f;   // advances by Ff per step

    for (int t = 0; t < Tt; ++t, gidx += Ff) {
        // ---- Stage A: load x, m, d; gamma_x --------------------------------
        const float xv = values[gidx];
        const float mv = masks[gidx];
        const float dv = deltas[gidx];
        xT[fr_f * 4 + fr_r] = xv;
        mT[fr_f * 4 + fr_r] = mv;
        actT[(64 + fr_f) * 4 + fr_r] = mv;
        dT[fr_f * 4 + fr_r] = dv;
        gxT[fr_f * 4 + fr_r] = __expf(-fmaxf(dv * g_wdx[fr_f] + b_dx[fr_f], 0.f));
        __syncthreads();

        // ---- Stage B: gamma_h, decay h (out hu, rows 2*hrp, 2*hrp+1) -------
        {
            float a0 = 0.f, a1 = 0.f;
#pragma unroll 8
            for (int k = 0; k < Ff; ++k) {
                const float w = g_WdhT[k * Hh + hu];
                const float2 ap = *reinterpret_cast<const float2*>(&dT[k * 4 + 2 * hrp]);
                a0 += w * ap.x;
                a1 += w * ap.y;
            }
            const float bb = b_dh[hu];
            actT[(128 + hu) * 4 + 2 * hrp]     *= __expf(-fmaxf(a0 + bb, 0.f));
            actT[(128 + hu) * 4 + 2 * hrp + 1] *= __expf(-fmaxf(a1 + bb, 0.f));
        }
        __syncthreads();

        // ---- Stage C: x_h (out fr_f, row fr_r) -----------------------------
        float x_h;
        {
            float acc = 0.f;
#pragma unroll 8
            for (int k = 0; k < Hh; ++k)
                acc += g_WhrT[k * Ff + fr_f] * actT[(128 + k) * 4 + fr_r];
            x_h = acc + b_hr[fr_f];
        }
        const float l1 = fabsf(xv - x_h) * mv;
        const float x_c = mv * xv + (1.f - mv) * x_h;
        xcT[fr_f * 4 + fr_r] = x_c;
        __syncthreads();

        // ---- Stage D: z_h, alpha, c_h, c_c, loss terms ---------------------
        float z_h, alpha;
        {
            float acc = 0.f;
#pragma unroll 8
            for (int k = 0; k < Ff; ++k)
                acc += g_WfrT[k * Ff + fr_f] * xcT[k * 4 + fr_r];
            z_h = acc + b_fr[fr_f];
            float acc2 = 0.f;
#pragma unroll 8
            for (int k = 0; k < Ff; ++k)
                acc2 += g_WwcT[k * Ff + fr_f] * gxT[k * 4 + fr_r];
#pragma unroll 8
            for (int k = 0; k < Ff; ++k)
                acc2 += g_WwcT[(64 + k) * Ff + fr_f] * mT[k * 4 + fr_r];
            alpha = acc2 + b_wc[fr_f];
        }
        const float c_h = alpha * z_h + (1.f - alpha) * x_h;
        const float l2 = fabsf(xv - z_h) * mv;
        const float l3 = fabsf(xv - c_h) * mv;
        lacc += (l1 + l2 + l3) * g_inv_msum[t];
        const float c_c = mv * xv + (1.f - mv) * c_h;
        out[1 + Bsz + gidx] = c_c;                 // imputations [B,T,F]
        actT[fr_f * 4 + fr_r] = c_c;
        __syncthreads();

        // ---- Stage E: gates GEMM (thread owns outs 2*tid, 2*tid+1; 4 rows) -
        {
            const int o0 = 2 * tid;
            unsigned long long acc00 = 0ull, acc01 = 0ull, acc10 = 0ull, acc11 = 0ull;
            const float2* wp = reinterpret_cast<const float2*>(&g_W[o0]);
#pragma unroll 8
            for (int k = 0; k < 256; ++k) {
                const float2 wv = wp[k * (Gg / 2)];
                const ulonglong2 av = *reinterpret_cast<const ulonglong2*>(&actT[k * 4]);
                const unsigned long long w0 = splat2(wv.x);
                const unsigned long long w1 = splat2(wv.y);
                acc00 = fma2(w0, av.x, acc00);
                acc01 = fma2(w0, av.y, acc01);
                acc10 = fma2(w1, av.x, acc10);
                acc11 = fma2(w1, av.y, acc11);
            }
            F2U u00, u01, u10, u11;
            u00.u = acc00; u01.u = acc01; u10.u = acc10; u11.u = acc11;
            const float bg0 = g_bg[o0], bg1 = g_bg[o0 + 1];
            *reinterpret_cast<float4*>(&gT[o0 * 4]) =
                make_float4(u00.f.x + bg0, u00.f.y + bg0, u01.f.x + bg0, u01.f.y + bg0);
            *reinterpret_cast<float4*>(&gT[(o0 + 1) * 4]) =
                make_float4(u10.f.x + bg1, u10.f.y + bg1, u11.f.x + bg1, u11.f.y + bg1);
        }
        __syncthreads();

        // ---- Stage F: LSTM update (out hu, rows 2*hrp, 2*hrp+1) ------------
#pragma unroll
        for (int s = 0; s < 2; ++s) {
            const int r = 2 * hrp + s;
            const float ig = gT[hu * 4 + r];
            const float fg = gT[(128 + hu) * 4 + r];
            const float gg = gT[(256 + hu) * 4 + r];
            const float og = gT[(384 + hu) * 4 + r];
            const float cn = sigm(fg) * cT[hu * 4 + r] + sigm(ig) * tanh_e(gg);
            cT[hu * 4 + r] = cn;
            actT[(128 + hu) * 4 + r] = sigm(og) * tanh_e(cn);
        }
        __syncthreads();
    }

    // ---- epilogue: x_loss block reduce ------------------------------------
    red[tid] = lacc; __syncthreads();
    for (int off = 128; off > 0; off >>= 1) {
        if (tid < off) red[tid] += red[tid + off];
        __syncthreads();
    }
    if (tid == 0) atomicAdd(&g_xloss, red[0]);

    // ---- epilogue: y head (warp w handles row w) --------------------------
    const int wid = tid >> 5, lid = tid & 31;
    if (wid < ROWS) {
        float s = 0.f;
#pragma unroll
        for (int u = lid; u < Hh; u += 32)
            s += actT[(128 + u) * 4 + wid] * W_out[u];
#pragma unroll
        for (int off = 16; off > 0; off >>= 1)
            s += __shfl_down_sync(0xffffffffu, s, off);
        if (lid == 0) {
            const int b = b0 + wid;
            const float yh = s + b_out[0];
            out[1 + b] = 1.f / (1.f + expf(-yh));           // predictions
            const float lab = labels[b];
            const float mx = fmaxf(-yh, 0.f);
            const float yl = yh - yh * lab + mx + logf(expf(-mx) + expf(-yh - mx));
            atomicAdd(&g_yloss, yl * is_train[b]);
        }
    }
}

// ---------------- finalize: combine loss ----------------------------------
__global__ void finalize_loss(float* __restrict__ out) {
    out[0] = g_xloss * (1.f / (float)Tt) + 0.3f * (g_yloss / (g_istrain + 1e-5f));
}

// ---------------- launch ---------------------------------------------------
extern "C" void kernel_launch(void* const* d_in, const int* in_sizes, int n_in,
                              void* d_out, int out_size) {
    (void)in_sizes; (void)n_in; (void)out_size;
    const float* values   = (const float*)d_in[0];
    const float* masks    = (const float*)d_in[1];
    const float* deltas   = (const float*)d_in[2];
    const float* labels   = (const float*)d_in[3];
    const float* is_train = (const float*)d_in[4];
    const float* W_dh = (const float*)d_in[5];
    const float* b_dh = (const float*)d_in[6];
    const float* W_dx = (const float*)d_in[7];
    const float* b_dx = (const float*)d_in[8];
    const float* W_hr = (const float*)d_in[9];
    const float* b_hr = (const float*)d_in[10];
    const float* W_fr = (const float*)d_in[11];
    const float* b_fr = (const float*)d_in[12];
    const float* W_wc = (const float*)d_in[13];
    const float* b_wc = (const float*)d_in[14];
    const float* W_ih = (const float*)d_in[15];
    const float* b_ih = (const float*)d_in[16];
    const float* W_hh = (const float*)d_in[17];
    const float* b_hh = (const float*)d_in[18];
    const float* W_out = (const float*)d_in[19];
    const float* b_out = (const float*)d_in[20];
    float* out = (float*)d_out;

    prep_weights<<<256, 256>>>(W_dh, W_dx, W_hr, W_fr, W_wc, W_ih, b_ih, W_hh, b_hh);
    prep_msum<<<Tt + 1, 256>>>(masks, is_train);
    brits_main<<<NCTA, 256>>>(values, masks, deltas, labels, is_train,
                              b_dh, b_dx, b_hr, b_fr, b_wc, W_out, b_out, out);
    finalize_loss<<<1, 1>>>(out);
}